// round 15
// baseline (speedup 1.0000x reference)
#include <cuda_runtime.h>
#include <math.h>
#include <stdint.h>

#define B_N   4
#define C_IN  64
#define C_OUT 64
#define H_IN  128
#define W_IN  128
#define H_OUT 126
#define W_OUT 126
#define CK    576            // 9 * 64
#define HWIN  (H_IN * W_IN)
#define HWOUT (H_OUT * W_OUT)
#define NFRAG2 (9 * 8 * 2 * 2 * 32 * 4)   // 36864 floats per main-weight array (nt4-packed)
#define NHLO   (9 * 8 * 4 * 32)           // offset-weight HL fragment groups (x4 floats)

// ---------------- scratch (device globals; no allocations allowed) ----------------
__device__ __align__(16) float g_xnhwc[B_N * HWIN * C_IN];        // 16 MB
__device__ __align__(16) float g_off[B_N * 27 * HWOUT];           // ~6.9 MB
__device__ __align__(16) float g_wBH[NFRAG2];                     // main W tf32-hi, nt4-packed
__device__ __align__(16) float g_wBL[NFRAG2];                     // main W residual, nt4-packed
__device__ __align__(16) float g_wOffFragHL[NHLO * 4];            // offset W: {h0,h1,l0,l1}

__device__ __forceinline__ float tf32_hi(float a) {
    return __uint_as_float(__float_as_uint(a) & 0xFFFFE000u);
}

__device__ __forceinline__ void mma_tf32(float* d, const uint4 a, const uint2 b) {
    asm volatile(
        "mma.sync.aligned.m16n8k8.row.col.f32.tf32.tf32.f32 "
        "{%0,%1,%2,%3},{%4,%5,%6,%7},{%8,%9},{%0,%1,%2,%3};"
        : "+f"(d[0]), "+f"(d[1]), "+f"(d[2]), "+f"(d[3])
        : "r"(a.x), "r"(a.y), "r"(a.z), "r"(a.w), "r"(b.x), "r"(b.y));
}

// ---------------- prep: NCHW -> NHWC transpose ----------------
__global__ void k_transpose_x(const float* __restrict__ x) {
    __shared__ float tile[32][33];
    int b   = blockIdx.z;
    int hw0 = blockIdx.x * 32;
    int c0  = blockIdx.y * 32;
    int tx = threadIdx.x, ty = threadIdx.y;
#pragma unroll
    for (int i = ty; i < 32; i += 8)
        tile[i][tx] = x[((size_t)(b * C_IN + c0 + i)) * HWIN + hw0 + tx];
    __syncthreads();
#pragma unroll
    for (int i = ty; i < 32; i += 8)
        g_xnhwc[((size_t)b * HWIN + hw0 + i) * C_IN + c0 + tx] = tile[tx][i];
}

// ---------------- prep: pack weights into B fragments ----------------
// B fragment (mma.m16n8k8.row.col): element e of lane = B[k=(lane&3)+4e][n=lane>>2]
// main (nt4-packed): g_wB*[ ((((k*8+s)*2+wn)*2+q)*32+lane)*4 + j ]
//   nt4 = 2q + (j>>1), e = j&1, nt = wn*4+nt4, o = nt*8+(lane>>2), c = s*8+(lane&3)+4e
// offset (interleaved): g_wOffFragHL[(((k*8+s)*4+nt)*32+lane)*4 + {h0,h1,l0,l1}], co>=27 -> 0
__global__ void k_prep_w(const float* __restrict__ w_off, const float* __restrict__ weight) {
    int t = blockIdx.x * blockDim.x + threadIdx.x;
    if (t < NFRAG2) {
        int j    = t & 3;
        int lane = (t >> 2) & 31;
        int q    = (t >> 7) & 1;
        int wn   = (t >> 8) & 1;
        int s    = (t >> 9) & 7;
        int k    = t >> 12;
        int nt4  = 2 * q + (j >> 1);
        int e    = j & 1;
        int o = (wn * 4 + nt4) * 8 + (lane >> 2);
        int c = s * 8 + (lane & 3) + 4 * e;
        float w  = weight[o * CK + c * 9 + k];
        float wh = tf32_hi(w);
        g_wBH[t] = wh;
        g_wBL[t] = w - wh;
    }
    if (t < NHLO) {
        int lane = t & 31;
        int nt   = (t >> 5) & 3;
        int s    = (t >> 7) & 7;
        int k    = t >> 10;
        int co = nt * 8 + (lane >> 2);
        int c0 = s * 8 + (lane & 3);
        float w0 = (co < 27) ? w_off[co * CK + c0 * 9 + k] : 0.f;
        float w1 = (co < 27) ? w_off[co * CK + (c0 + 4) * 9 + k] : 0.f;
        float h0 = tf32_hi(w0), h1 = tf32_hi(w1);
        float4 v = make_float4(h0, h1, w0 - h0, w1 - h1);
        *(float4*)&g_wOffFragHL[t * 4] = v;
    }
}

// ---------------- offset conv via 2xTF32 MMA: x (NHWC) -> g_off ----------------
#define SMEM_O (8192 * 4)

__global__ __launch_bounds__(256, 4) void k_offset_mma(const float* __restrict__ b_off) {
    extern __shared__ float sm[];
    float* S = sm;                   // [8192] A-fragment layout; reused for staging

    int b  = blockIdx.z;
    int ho = blockIdx.y;
    int t  = threadIdx.x;

    const float* xb = g_xnhwc + b * (HWIN * C_IN);

    int lane = t & 31;
    int wrp  = t >> 5;               // pixel group: px [wrp*16, wrp*16+16)
    int t4   = lane & 3, gid = lane >> 2;

    float acc[4][4];                 // [nt4][reg]
#pragma unroll
    for (int j = 0; j < 4; j++)
#pragma unroll
        for (int r = 0; r < 4; r++) acc[j][r] = 0.f;

    for (int k = 0; k < 9; k++) {
        int kh = k / 3, kw = k - kh * 3;
        const float* xrow = xb + ((ho + kh) * W_IN) * C_IN;

        // ---- A fill: regular loads (clamped col; only invalid outputs affected) ----
#pragma unroll
        for (int it = 0; it < 8; it++) {
            int j  = t + it * 256;
            int cg = j & 15;
            int p  = j >> 4;
            int cq = cg << 2;
            int wc = min(p + kw, W_IN - 1);
            float4 v = *(const float4*)(xrow + wc * C_IN + cq);
            int s    = cg >> 1;
            int reg  = ((p >> 3) & 1) + 2 * (cg & 1);
            int base = (((p >> 4) * 8) + s) * 128 + reg;
            int gl4  = (p & 7) << 2;
            float rv[4] = { v.x, v.y, v.z, v.w };
#pragma unroll
            for (int u = 0; u < 4; u++)
                S[base + (((gl4 | u) ^ s) << 2)] = rv[u];
        }
        __syncthreads();

        // ---- 2xTF32 MMA ----
#pragma unroll
        for (int s = 0; s < 8; s++) {
            int aoff = (lane ^ s) << 2;
            float4 Af = *(const float4*)&S[(wrp * 8 + s) * 128 + aoff];
            float4 Ahf, Alf;
            Ahf.x = tf32_hi(Af.x); Alf.x = Af.x - Ahf.x;
            Ahf.y = tf32_hi(Af.y); Alf.y = Af.y - Ahf.y;
            Ahf.z = tf32_hi(Af.z); Alf.z = Af.z - Ahf.z;
            Ahf.w = tf32_hi(Af.w); Alf.w = Af.w - Ahf.w;
            uint4 Ah = *(uint4*)&Ahf, Al = *(uint4*)&Alf;
            int fb = (((k * 8 + s) * 4) * 32 + lane) * 4;
#pragma unroll
            for (int nt4 = 0; nt4 < 4; nt4++) {
                uint4 BHL = *(const uint4*)&g_wOffFragHL[fb + nt4 * 128];
                uint2 Bh = make_uint2(BHL.x, BHL.y);
                mma_tf32(acc[nt4], Ah, Bh);
                mma_tf32(acc[nt4], Al, Bh);
            }
        }
        __syncthreads();
    }

    // ---- epilogue: bias + sigmoid(ch>=18), stage [co][p] pitch 132, coalesced g_off stores ----
    float* st = sm;                  // [32][132] = 4224 <= 8192
#pragma unroll
    for (int nt4 = 0; nt4 < 4; nt4++) {
        int co0 = nt4 * 8 + t4 * 2;
#pragma unroll
        for (int e = 0; e < 2; e++) {
            int co = co0 + e;
            float bb = (co < 27) ? b_off[co] : 0.f;
            float v0 = acc[nt4][e]     + bb;    // row gid
            float v1 = acc[nt4][e + 2] + bb;    // row gid+8
            if (co >= 18) {
                v0 = 1.f / (1.f + expf(-v0));
                v1 = 1.f / (1.f + expf(-v1));
            }
            st[co * 132 + wrp * 16 + gid]     = v0;
            st[co * 132 + wrp * 16 + gid + 8] = v1;
        }
    }
    __syncthreads();
    int obase = (b * 27) * HWOUT + ho * W_OUT;
    for (int i = t; i < 27 * 128; i += 256) {
        int co = i >> 7, wo = i & 127;
        if (wo < W_OUT)
            g_off[obase + co * HWOUT + wo] = st[co * 132 + wo];
    }
}

// ---------------- fused deform-sample + 3xTF32 MMA GEMM + bias + ReLU ----------------
// Double-buffered S: sampling of tap k+1 overlaps MMA of tap k in the same
// barrier interval (one __syncthreads per tap). 128 threads, 64 px x 64 out,
// warp tile 32x32; B fragments nt4-packed, hoisted across the mt loop.
#define SMEM_B (8192 * 4)   // two S buffers (2 x 4096); epilogue reuses 4352

__global__ __launch_bounds__(128, 6) void k_deform_gemm(const float* __restrict__ bias,
                                                        float* __restrict__ out) {
    extern __shared__ float sm[];

    int b   = blockIdx.z;
    int ho  = blockIdx.y;
    int px0 = blockIdx.x * 64;       // pixel base of this half-row
    int t   = threadIdx.x;

    const float* xb = g_xnhwc + b * (HWIN * C_IN);
    int obase = ((b * 27) * H_OUT + ho) * W_OUT;

    int lane = t & 31;
    int wrp  = t >> 5;               // 0..3
    int wm   = wrp & 1;              // M-tile: pixels [px0 + wm*32, +32)
    int wn   = wrp >> 1;             // N-tile: outputs [wn*32, wn*32+32)
    int t4   = lane & 3, gid = lane >> 2;

    float acc[2][4][4];              // [mt][nt4][reg]
#pragma unroll
    for (int i = 0; i < 2; i++)
#pragma unroll
        for (int j = 0; j < 4; j++)
#pragma unroll
            for (int r = 0; r < 4; r++) acc[i][j][r] = 0.f;

    // sampling lambda: fill buffer `Sb` for tap `k`
    auto sample_tap = [&](int k, float* Sb) {
        int kh = k / 3, kw = k - kh * 3;
#pragma unroll
        for (int it = 0; it < 8; it++) {
            int j  = t + it * 128;
            int cg = j & 15;             // channel group (cq = cg*4)
            int pl = j >> 4;             // pixel-in-block 0..63
            int p  = px0 + pl;           // global pixel
            int cq = cg << 2;
            int wo = min(p, W_OUT - 1);
            // interleaved layout: off_y[k] = ch 2k, off_x[k] = ch 2k+1, mask = ch 18+k
            float oy = g_off[obase + wo + (2 * k)     * HWOUT];
            float ox = g_off[obase + wo + (2 * k + 1) * HWOUT];
            float m  = g_off[obase + wo + (18 + k)    * HWOUT];
            float ys = (float)(ho + kh) + oy;
            float xs = (float)(wo + kw) + ox;
            float yf = floorf(ys), xf = floorf(xs);
            float wy = ys - yf, wx = xs - xf;
            int y0 = (int)yf, x0 = (int)xf;
            float w00 = (1.f - wy) * (1.f - wx) * m;
            float w01 = (1.f - wy) * wx * m;
            float w10 = wy * (1.f - wx) * m;
            float w11 = wy * wx * m;
            int y1 = y0 + 1, x1 = x0 + 1;
            float rv[4] = {0.f, 0.f, 0.f, 0.f};
            if ((unsigned)y0 < (unsigned)H_IN) {
                const float* row = xb + (y0 * W_IN) * C_IN + cq;
                if ((unsigned)x0 < (unsigned)W_IN) {
                    float4 v = *(const float4*)(row + x0 * C_IN);
                    rv[0] += w00 * v.x; rv[1] += w00 * v.y; rv[2] += w00 * v.z; rv[3] += w00 * v.w;
                }
                if ((unsigned)x1 < (unsigned)W_IN) {
                    float4 v = *(const float4*)(row + x1 * C_IN);
                    rv[0] += w01 * v.x; rv[1] += w01 * v.y; rv[2] += w01 * v.z; rv[3] += w01 * v.w;
                }
            }
            if ((unsigned)y1 < (unsigned)H_IN) {
                const float* row = xb + (y1 * W_IN) * C_IN + cq;
                if ((unsigned)x0 < (unsigned)W_IN) {
                    float4 v = *(const float4*)(row + x0 * C_IN);
                    rv[0] += w10 * v.x; rv[1] += w10 * v.y; rv[2] += w10 * v.z; rv[3] += w10 * v.w;
                }
                if ((unsigned)x1 < (unsigned)W_IN) {
                    float4 v = *(const float4*)(row + x1 * C_IN);
                    rv[0] += w11 * v.x; rv[1] += w11 * v.y; rv[2] += w11 * v.z; rv[3] += w11 * v.w;
                }
            }
            // scatter into A-fragment slots (XOR-by-s swizzle), indexed by pl
            int s    = cg >> 1;
            int reg  = ((pl >> 3) & 1) + 2 * (cg & 1);
            int base = (((pl >> 4) * 8) + s) * 128 + reg;   // pl>>4 = wm*2+mt
            int gl4  = (pl & 7) << 2;
#pragma unroll
            for (int u = 0; u < 4; u++)
                Sb[base + (((gl4 | u) ^ s) << 2)] = rv[u];
        }
    };

    // ---- prologue: fill buffer 0 with tap 0 ----
    sample_tap(0, sm);
    __syncthreads();

    for (int k = 0; k < 9; k++) {
        float* cur = sm + ((k & 1) << 12);
        float* nxt = sm + (((k + 1) & 1) << 12);

        // sample tap k+1 into the other buffer (overlaps with this tap's MMAs
        // across warps in the same barrier interval)
        if (k < 8) sample_tap(k + 1, nxt);

        // ---- 3xTF32 MMA on cur: 8 ksteps; B held in regs across the mt loop ----
#pragma unroll
        for (int s = 0; s < 8; s++) {
            int aoff = (lane ^ s) << 2;
            int fb   = ((((k * 8 + s) * 2 + wn) * 2) * 32 + lane) * 4;
            uint4 BH0 = *(const uint4*)&g_wBH[fb];
            uint4 BH1 = *(const uint4*)&g_wBH[fb + 128];
            uint4 BL0 = *(const uint4*)&g_wBL[fb];
            uint4 BL1 = *(const uint4*)&g_wBL[fb + 128];
#pragma unroll
            for (int mt = 0; mt < 2; mt++) {
                float4 Af = *(const float4*)&cur[((wm * 2 + mt) * 8 + s) * 128 + aoff];
                float4 Ahf, Alf;
                Ahf.x = tf32_hi(Af.x); Alf.x = Af.x - Ahf.x;
                Ahf.y = tf32_hi(Af.y); Alf.y = Af.y - Ahf.y;
                Ahf.z = tf32_hi(Af.z); Alf.z = Af.z - Ahf.z;
                Ahf.w = tf32_hi(Af.w); Alf.w = Af.w - Ahf.w;
                uint4 Ah = *(uint4*)&Ahf, Al = *(uint4*)&Alf;
                mma_tf32(acc[mt][0], Ah, make_uint2(BH0.x, BH0.y));
                mma_tf32(acc[mt][0], Al, make_uint2(BH0.x, BH0.y));
                mma_tf32(acc[mt][0], Ah, make_uint2(BL0.x, BL0.y));
                mma_tf32(acc[mt][1], Ah, make_uint2(BH0.z, BH0.w));
                mma_tf32(acc[mt][1], Al, make_uint2(BH0.z, BH0.w));
                mma_tf32(acc[mt][1], Ah, make_uint2(BL0.z, BL0.w));
                mma_tf32(acc[mt][2], Ah, make_uint2(BH1.x, BH1.y));
                mma_tf32(acc[mt][2], Al, make_uint2(BH1.x, BH1.y));
                mma_tf32(acc[mt][2], Ah, make_uint2(BL1.x, BL1.y));
                mma_tf32(acc[mt][3], Ah, make_uint2(BH1.z, BH1.w));
                mma_tf32(acc[mt][3], Al, make_uint2(BH1.z, BH1.w));
                mma_tf32(acc[mt][3], Ah, make_uint2(BL1.z, BL1.w));
            }
        }
        // one barrier per tap: cur reads done before it's refilled next iter;
        // nxt writes visible before next iter's MMA reads it
        __syncthreads();
    }

    // ---- epilogue: stage [o][pl] in smem (pitch 68), coalesced stores + bias + ReLU ----
    float* outS = sm;                // 64*68 = 4352 floats
#pragma unroll
    for (int mt = 0; mt < 2; mt++) {
        int p0 = wm * 32 + mt * 16 + gid;       // pixel-in-block
#pragma unroll
        for (int nt4 = 0; nt4 < 4; nt4++) {
            int n0 = (wn * 4 + nt4) * 8 + t4 * 2;
            outS[(n0 + 0) * 68 + p0]     = acc[mt][nt4][0];
            outS[(n0 + 1) * 68 + p0]     = acc[mt][nt4][1];
            outS[(n0 + 0) * 68 + p0 + 8] = acc[mt][nt4][2];
            outS[(n0 + 1) * 68 + p0 + 8] = acc[mt][nt4][3];
        }
    }
    __syncthreads();
    for (int i = t; i < 64 * 64; i += 128) {
        int o = i >> 6, pl = i & 63;
        int pp = px0 + pl;
        if (pp < W_OUT) {
            float v = outS[o * 68 + pl] + bias[o];
            out[((b * C_OUT + o) * H_OUT + ho) * W_OUT + pp] = fmaxf(v, 0.f);
        }
    }
}

// ---------------- launch ----------------
extern "C" void kernel_launch(void* const* d_in, const int* in_sizes, int n_in,
                              void* d_out, int out_size) {
    const float* x      = (const float*)d_in[0];
    const float* w_off  = (const float*)d_in[1];
    const float* b_off  = (const float*)d_in[2];
    const float* weight = (const float*)d_in[3];
    const float* bias   = (const float*)d_in[4];
    float* out = (float*)d_out;
    (void)in_sizes; (void)n_in; (void)out_size;

    cudaFuncSetAttribute(k_offset_mma,  cudaFuncAttributeMaxDynamicSharedMemorySize, SMEM_O);
    cudaFuncSetAttribute(k_deform_gemm, cudaFuncAttributeMaxDynamicSharedMemorySize, SMEM_B);

    k_transpose_x<<<dim3(HWIN / 32, C_IN / 32, B_N), dim3(32, 8)>>>(x);
    k_prep_w<<<(NFRAG2 + 255) / 256, 256>>>(w_off, weight);
    k_offset_mma<<<dim3(1, H_OUT, B_N), 256, SMEM_O>>>(b_off);
    k_deform_gemm<<<dim3(2, H_OUT, B_N), 128, SMEM_B>>>(bias, out);
}

// round 16
// speedup vs baseline: 1.3944x; 1.3944x over previous
#include <cuda_runtime.h>
#include <math.h>
#include <stdint.h>

#define B_N   4
#define C_IN  64
#define C_OUT 64
#define H_IN  128
#define W_IN  128
#define H_OUT 126
#define W_OUT 126
#define CK    576            // 9 * 64
#define HWIN  (H_IN * W_IN)
#define HWOUT (H_OUT * W_OUT)
#define NFRAG2 (9 * 8 * 2 * 2 * 32 * 4)   // 36864 floats per main-weight array (nt4-packed)
#define NHLO   (9 * 8 * 4 * 32)           // offset-weight HL fragment groups (x4 floats)

// ---------------- scratch (device globals; no allocations allowed) ----------------
__device__ __align__(16) float g_xnhwc[B_N * HWIN * C_IN];        // 16 MB
__device__ __align__(16) float g_off[B_N * 27 * HWOUT];           // ~6.9 MB
__device__ __align__(16) float g_wBH[NFRAG2];                     // main W tf32-hi, nt4-packed
__device__ __align__(16) float g_wBL[NFRAG2];                     // main W residual, nt4-packed
__device__ __align__(16) float g_wOffFragHL[NHLO * 4];            // offset W: {h0,h1,l0,l1}

__device__ __forceinline__ float tf32_hi(float a) {
    return __uint_as_float(__float_as_uint(a) & 0xFFFFE000u);
}

__device__ __forceinline__ void mma_tf32(float* d, const uint4 a, const uint2 b) {
    asm volatile(
        "mma.sync.aligned.m16n8k8.row.col.f32.tf32.tf32.f32 "
        "{%0,%1,%2,%3},{%4,%5,%6,%7},{%8,%9},{%0,%1,%2,%3};"
        : "+f"(d[0]), "+f"(d[1]), "+f"(d[2]), "+f"(d[3])
        : "r"(a.x), "r"(a.y), "r"(a.z), "r"(a.w), "r"(b.x), "r"(b.y));
}

// ---------------- prep: NCHW -> NHWC transpose ----------------
__global__ void k_transpose_x(const float* __restrict__ x) {
    __shared__ float tile[32][33];
    int b   = blockIdx.z;
    int hw0 = blockIdx.x * 32;
    int c0  = blockIdx.y * 32;
    int tx = threadIdx.x, ty = threadIdx.y;
#pragma unroll
    for (int i = ty; i < 32; i += 8)
        tile[i][tx] = x[((size_t)(b * C_IN + c0 + i)) * HWIN + hw0 + tx];
    __syncthreads();
#pragma unroll
    for (int i = ty; i < 32; i += 8)
        g_xnhwc[((size_t)b * HWIN + hw0 + i) * C_IN + c0 + tx] = tile[tx][i];
}

// ---------------- prep: pack weights into B fragments ----------------
// B fragment (mma.m16n8k8.row.col): element e of lane = B[k=(lane&3)+4e][n=lane>>2]
// main (nt4-packed): g_wB*[ ((((k*8+s)*2+wn)*2+q)*32+lane)*4 + j ]
//   nt4 = 2q + (j>>1), e = j&1, nt = wn*4+nt4, o = nt*8+(lane>>2), c = s*8+(lane&3)+4e
// offset (interleaved): g_wOffFragHL[(((k*8+s)*4+nt)*32+lane)*4 + {h0,h1,l0,l1}], co>=27 -> 0
__global__ void k_prep_w(const float* __restrict__ w_off, const float* __restrict__ weight) {
    int t = blockIdx.x * blockDim.x + threadIdx.x;
    if (t < NFRAG2) {
        int j    = t & 3;
        int lane = (t >> 2) & 31;
        int q    = (t >> 7) & 1;
        int wn   = (t >> 8) & 1;
        int s    = (t >> 9) & 7;
        int k    = t >> 12;
        int nt4  = 2 * q + (j >> 1);
        int e    = j & 1;
        int o = (wn * 4 + nt4) * 8 + (lane >> 2);
        int c = s * 8 + (lane & 3) + 4 * e;
        float w  = weight[o * CK + c * 9 + k];
        float wh = tf32_hi(w);
        g_wBH[t] = wh;
        g_wBL[t] = w - wh;
    }
    if (t < NHLO) {
        int lane = t & 31;
        int nt   = (t >> 5) & 3;
        int s    = (t >> 7) & 7;
        int k    = t >> 10;
        int co = nt * 8 + (lane >> 2);
        int c0 = s * 8 + (lane & 3);
        float w0 = (co < 27) ? w_off[co * CK + c0 * 9 + k] : 0.f;
        float w1 = (co < 27) ? w_off[co * CK + (c0 + 4) * 9 + k] : 0.f;
        float h0 = tf32_hi(w0), h1 = tf32_hi(w1);
        float4 v = make_float4(h0, h1, w0 - h0, w1 - h1);
        *(float4*)&g_wOffFragHL[t * 4] = v;
    }
}

// ---------------- offset conv via 2xTF32 MMA: x (NHWC) -> g_off ----------------
// 128 threads (4 warps), tile = 64 px x 32 chans (27 valid). Warp wrp owns
// 16 px x 32 out. Same A-fragment layout / swizzle as deform; grid 2 x 126 x 4
// for finer SM balance (mirrors the R13 deform win). smem 16 KB -> 8 blocks/SM.
#define SMEM_O (4096 * 4)

__global__ __launch_bounds__(128, 8) void k_offset_mma(const float* __restrict__ b_off) {
    extern __shared__ float sm[];
    float* S = sm;                   // [4096] A-fragment layout; reused for staging

    int b   = blockIdx.z;
    int ho  = blockIdx.y;
    int px0 = blockIdx.x * 64;
    int t   = threadIdx.x;

    const float* xb = g_xnhwc + b * (HWIN * C_IN);

    int lane = t & 31;
    int wrp  = t >> 5;               // pixel group: px [px0 + wrp*16, +16)
    int t4   = lane & 3, gid = lane >> 2;

    float acc[4][4];                 // [nt4][reg]
#pragma unroll
    for (int j = 0; j < 4; j++)
#pragma unroll
        for (int r = 0; r < 4; r++) acc[j][r] = 0.f;

    for (int k = 0; k < 9; k++) {
        int kh = k / 3, kw = k - kh * 3;
        const float* xrow = xb + ((ho + kh) * W_IN) * C_IN;

        // ---- A fill: regular loads (clamped col; only invalid outputs affected) ----
#pragma unroll
        for (int it = 0; it < 8; it++) {
            int j  = t + it * 128;
            int cg = j & 15;
            int pl = j >> 4;             // pixel-in-block 0..63
            int cq = cg << 2;
            int wc = min(px0 + pl + kw, W_IN - 1);
            float4 v = *(const float4*)(xrow + wc * C_IN + cq);
            int s    = cg >> 1;
            int reg  = ((pl >> 3) & 1) + 2 * (cg & 1);
            int base = (((pl >> 4) * 8) + s) * 128 + reg;
            int gl4  = (pl & 7) << 2;
            float rv[4] = { v.x, v.y, v.z, v.w };
#pragma unroll
            for (int u = 0; u < 4; u++)
                S[base + (((gl4 | u) ^ s) << 2)] = rv[u];
        }
        __syncthreads();

        // ---- 2xTF32 MMA ----
#pragma unroll
        for (int s = 0; s < 8; s++) {
            int aoff = (lane ^ s) << 2;
            float4 Af = *(const float4*)&S[(wrp * 8 + s) * 128 + aoff];
            float4 Ahf, Alf;
            Ahf.x = tf32_hi(Af.x); Alf.x = Af.x - Ahf.x;
            Ahf.y = tf32_hi(Af.y); Alf.y = Af.y - Ahf.y;
            Ahf.z = tf32_hi(Af.z); Alf.z = Af.z - Ahf.z;
            Ahf.w = tf32_hi(Af.w); Alf.w = Af.w - Ahf.w;
            uint4 Ah = *(uint4*)&Ahf, Al = *(uint4*)&Alf;
            int fb = (((k * 8 + s) * 4) * 32 + lane) * 4;
#pragma unroll
            for (int nt4 = 0; nt4 < 4; nt4++) {
                uint4 BHL = *(const uint4*)&g_wOffFragHL[fb + nt4 * 128];
                uint2 Bh = make_uint2(BHL.x, BHL.y);
                mma_tf32(acc[nt4], Ah, Bh);
                mma_tf32(acc[nt4], Al, Bh);
            }
        }
        __syncthreads();
    }

    // ---- epilogue: bias + sigmoid(ch>=18), stage [co][pl] pitch 68, coalesced stores ----
    float* st = sm;                  // [32][68] = 2176 <= 4096
#pragma unroll
    for (int nt4 = 0; nt4 < 4; nt4++) {
        int co0 = nt4 * 8 + t4 * 2;
#pragma unroll
        for (int e = 0; e < 2; e++) {
            int co = co0 + e;
            float bb = (co < 27) ? b_off[co] : 0.f;
            float v0 = acc[nt4][e]     + bb;    // row gid
            float v1 = acc[nt4][e + 2] + bb;    // row gid+8
            if (co >= 18) {
                v0 = 1.f / (1.f + expf(-v0));
                v1 = 1.f / (1.f + expf(-v1));
            }
            st[co * 68 + wrp * 16 + gid]     = v0;
            st[co * 68 + wrp * 16 + gid + 8] = v1;
        }
    }
    __syncthreads();
    int obase = (b * 27) * HWOUT + ho * W_OUT;
    for (int i = t; i < 27 * 64; i += 128) {
        int co = i >> 6, pl = i & 63;
        int wo = px0 + pl;
        if (wo < W_OUT)
            g_off[obase + co * HWOUT + wo] = st[co * 68 + pl];
    }
}

// ---------------- fused deform-sample + 3xTF32 MMA GEMM + bias + ReLU ----------------
// R14-proven form (best measured: 132 us): 128 threads, 64 px x 64 out, warp
// tile 32x32; B fragments nt4-packed (2 contiguous LDG.128/array/kstep) hoisted
// across the mt loop; params inline; single S buffer, 2 barriers/tap.
#define SMEM_B (4352 * 4)   // max(S 4096, epilogue 64*68) floats

__global__ __launch_bounds__(128, 7) void k_deform_gemm(const float* __restrict__ bias,
                                                        float* __restrict__ out) {
    extern __shared__ float sm[];
    float* S = sm;                   // [4096] A-fragment layout (2 M-tiles)

    int b   = blockIdx.z;
    int ho  = blockIdx.y;
    int px0 = blockIdx.x * 64;       // pixel base of this half-row
    int t   = threadIdx.x;

    const float* xb = g_xnhwc + b * (HWIN * C_IN);
    int obase = ((b * 27) * H_OUT + ho) * W_OUT;

    int lane = t & 31;
    int wrp  = t >> 5;               // 0..3
    int wm   = wrp & 1;              // M-tile: pixels [px0 + wm*32, +32)
    int wn   = wrp >> 1;             // N-tile: outputs [wn*32, wn*32+32)
    int t4   = lane & 3, gid = lane >> 2;

    float acc[2][4][4];              // [mt][nt4][reg]
#pragma unroll
    for (int i = 0; i < 2; i++)
#pragma unroll
        for (int j = 0; j < 4; j++)
#pragma unroll
            for (int r = 0; r < 4; r++) acc[i][j][r] = 0.f;

    for (int k = 0; k < 9; k++) {
        int kh = k / 3, kw = k - kh * 3;

        // ---- bilinear sampling into A-fragment layout (1024 items / 128 threads) ----
#pragma unroll
        for (int it = 0; it < 8; it++) {
            int j  = t + it * 128;
            int cg = j & 15;             // channel group (cq = cg*4)
            int pl = j >> 4;             // pixel-in-block 0..63
            int p  = px0 + pl;           // global pixel
            int cq = cg << 2;
            int wo = min(p, W_OUT - 1);
            // interleaved layout: off_y[k] = ch 2k, off_x[k] = ch 2k+1, mask = ch 18+k
            float oy = g_off[obase + wo + (2 * k)     * HWOUT];
            float ox = g_off[obase + wo + (2 * k + 1) * HWOUT];
            float m  = g_off[obase + wo + (18 + k)    * HWOUT];
            float ys = (float)(ho + kh) + oy;
            float xs = (float)(wo + kw) + ox;
            float yf = floorf(ys), xf = floorf(xs);
            float wy = ys - yf, wx = xs - xf;
            int y0 = (int)yf, x0 = (int)xf;
            float w00 = (1.f - wy) * (1.f - wx) * m;
            float w01 = (1.f - wy) * wx * m;
            float w10 = wy * (1.f - wx) * m;
            float w11 = wy * wx * m;
            int y1 = y0 + 1, x1 = x0 + 1;
            float rv[4] = {0.f, 0.f, 0.f, 0.f};
            if ((unsigned)y0 < (unsigned)H_IN) {
                const float* row = xb + (y0 * W_IN) * C_IN + cq;
                if ((unsigned)x0 < (unsigned)W_IN) {
                    float4 v = *(const float4*)(row + x0 * C_IN);
                    rv[0] += w00 * v.x; rv[1] += w00 * v.y; rv[2] += w00 * v.z; rv[3] += w00 * v.w;
                }
                if ((unsigned)x1 < (unsigned)W_IN) {
                    float4 v = *(const float4*)(row + x1 * C_IN);
                    rv[0] += w01 * v.x; rv[1] += w01 * v.y; rv[2] += w01 * v.z; rv[3] += w01 * v.w;
                }
            }
            if ((unsigned)y1 < (unsigned)H_IN) {
                const float* row = xb + (y1 * W_IN) * C_IN + cq;
                if ((unsigned)x0 < (unsigned)W_IN) {
                    float4 v = *(const float4*)(row + x0 * C_IN);
                    rv[0] += w10 * v.x; rv[1] += w10 * v.y; rv[2] += w10 * v.z; rv[3] += w10 * v.w;
                }
                if ((unsigned)x1 < (unsigned)W_IN) {
                    float4 v = *(const float4*)(row + x1 * C_IN);
                    rv[0] += w11 * v.x; rv[1] += w11 * v.y; rv[2] += w11 * v.z; rv[3] += w11 * v.w;
                }
            }
            // scatter into A-fragment slots (XOR-by-s swizzle), indexed by pl
            int s    = cg >> 1;
            int reg  = ((pl >> 3) & 1) + 2 * (cg & 1);
            int base = (((pl >> 4) * 8) + s) * 128 + reg;   // pl>>4 = wm*2+mt
            int gl4  = (pl & 7) << 2;
#pragma unroll
            for (int u = 0; u < 4; u++)
                S[base + (((gl4 | u) ^ s) << 2)] = rv[u];
        }
        __syncthreads();

        // ---- 3xTF32 MMA: 8 ksteps; B held in regs across the mt loop ----
#pragma unroll
        for (int s = 0; s < 8; s++) {
            int aoff = (lane ^ s) << 2;
            int fb   = ((((k * 8 + s) * 2 + wn) * 2) * 32 + lane) * 4;
            uint4 BH0 = *(const uint4*)&g_wBH[fb];
            uint4 BH1 = *(const uint4*)&g_wBH[fb + 128];
            uint4 BL0 = *(const uint4*)&g_wBL[fb];
            uint4 BL1 = *(const uint4*)&g_wBL[fb + 128];
#pragma unroll
            for (int mt = 0; mt < 2; mt++) {
                float4 Af = *(const float4*)&S[((wm * 2 + mt) * 8 + s) * 128 + aoff];
                float4 Ahf, Alf;
                Ahf.x = tf32_hi(Af.x); Alf.x = Af.x - Ahf.x;
                Ahf.y = tf32_hi(Af.y); Alf.y = Af.y - Ahf.y;
                Ahf.z = tf32_hi(Af.z); Alf.z = Af.z - Ahf.z;
                Ahf.w = tf32_hi(Af.w); Alf.w = Af.w - Ahf.w;
                uint4 Ah = *(uint4*)&Ahf, Al = *(uint4*)&Alf;
                mma_tf32(acc[mt][0], Ah, make_uint2(BH0.x, BH0.y));
                mma_tf32(acc[mt][0], Al, make_uint2(BH0.x, BH0.y));
                mma_tf32(acc[mt][0], Ah, make_uint2(BL0.x, BL0.y));
                mma_tf32(acc[mt][1], Ah, make_uint2(BH0.z, BH0.w));
                mma_tf32(acc[mt][1], Al, make_uint2(BH0.z, BH0.w));
                mma_tf32(acc[mt][1], Ah, make_uint2(BL0.z, BL0.w));
                mma_tf32(acc[mt][2], Ah, make_uint2(BH1.x, BH1.y));
                mma_tf32(acc[mt][2], Al, make_uint2(BH1.x, BH1.y));
                mma_tf32(acc[mt][2], Ah, make_uint2(BL1.x, BL1.y));
                mma_tf32(acc[mt][3], Ah, make_uint2(BH1.z, BH1.w));
                mma_tf32(acc[mt][3], Al, make_uint2(BH1.z, BH1.w));
                mma_tf32(acc[mt][3], Ah, make_uint2(BL1.z, BL1.w));
            }
        }
        __syncthreads();             // S free for next tap's sampling
    }

    // ---- epilogue: stage [o][pl] in smem (pitch 68), coalesced stores + bias + ReLU ----
    float* outS = sm;                // 64*68 = 4352 floats
#pragma unroll
    for (int mt = 0; mt < 2; mt++) {
        int p0 = wm * 32 + mt * 16 + gid;       // pixel-in-block
#pragma unroll
        for (int nt4 = 0; nt4 < 4; nt4++) {
            int n0 = (wn * 4 + nt4) * 8 + t4 * 2;
            outS[(n0 + 0) * 68 + p0]     = acc[mt][nt4][0];
            outS[(n0 + 1) * 68 + p0]     = acc[mt][nt4][1];
            outS[(n0 + 0) * 68 + p0 + 8] = acc[mt][nt4][2];
            outS[(n0 + 1) * 68 + p0 + 8] = acc[mt][nt4][3];
        }
    }
    __syncthreads();
    for (int i = t; i < 64 * 64; i += 128) {
        int o = i >> 6, pl = i & 63;
        int pp = px0 + pl;
        if (pp < W_OUT) {
            float v = outS[o * 68 + pl] + bias[o];
            out[((b * C_OUT + o) * H_OUT + ho) * W_OUT + pp] = fmaxf(v, 0.f);
        }
    }
}

// ---------------- launch ----------------
extern "C" void kernel_launch(void* const* d_in, const int* in_sizes, int n_in,
                              void* d_out, int out_size) {
    const float* x      = (const float*)d_in[0];
    const float* w_off  = (const float*)d_in[1];
    const float* b_off  = (const float*)d_in[2];
    const float* weight = (const float*)d_in[3];
    const float* bias   = (const float*)d_in[4];
    float* out = (float*)d_out;
    (void)in_sizes; (void)n_in; (void)out_size;

    cudaFuncSetAttribute(k_offset_mma,  cudaFuncAttributeMaxDynamicSharedMemorySize, SMEM_O);
    cudaFuncSetAttribute(k_deform_gemm, cudaFuncAttributeMaxDynamicSharedMemorySize, SMEM_B);

    k_transpose_x<<<dim3(HWIN / 32, C_IN / 32, B_N), dim3(32, 8)>>>(x);
    k_prep_w<<<(NFRAG2 + 255) / 256, 256>>>(w_off, weight);
    k_offset_mma<<<dim3(2, H_OUT, B_N), 128, SMEM_O>>>(b_off);
    k_deform_gemm<<<dim3(2, H_OUT, B_N), 128, SMEM_B>>>(bias, out);
}